// round 14
// baseline (speedup 1.0000x reference)
#include <cuda_runtime.h>
#include <cstdint>

#define L2E 1.4426950408889634f
#define LN2 0.6931471805599453f

// Inter-kernel (Y, m) scratch + permuted weights (static device mem: allowed)
__device__ float g_Y1[(size_t)512 * 128 * 32];   // 8 MB
__device__ float g_m1[(size_t)512 * 128];
__device__ float g_Wp[(size_t)2047 * 1024];      // 8 MB, fragment-ordered W

// ---------------------------------------------------------------------------
__device__ __forceinline__ float ex2f(float x) {
    float r; asm("ex2.approx.f32 %0, %1;" : "=f"(r) : "f"(x)); return r;
}
__device__ __forceinline__ float lg2f(float x) {
    float r; asm("lg2.approx.f32 %0, %1;" : "=f"(r) : "f"(x)); return r;
}
__device__ __forceinline__ float rcpf(float x) {
    float r; asm("rcp.approx.f32 %0, %1;" : "=f"(r) : "f"(x)); return r;
}
// m16n8k8 tf32 mma, D += A*B (A passed as f32, truncated by HW)
__device__ __forceinline__ void mma_tf32(float c[4], const float a[4], const uint32_t b[2]) {
    asm("mma.sync.aligned.m16n8k8.row.col.f32.tf32.tf32.f32 "
        "{%0,%1,%2,%3}, {%4,%5,%6,%7}, {%8,%9}, {%0,%1,%2,%3};"
        : "+f"(c[0]), "+f"(c[1]), "+f"(c[2]), "+f"(c[3])
        : "r"(__float_as_uint(a[0])), "r"(__float_as_uint(a[1])),
          "r"(__float_as_uint(a[2])), "r"(__float_as_uint(a[3])),
          "r"(b[0]), "r"(b[1]));
}

// ---------------------------------------------------------------------------
// W permute: Wp[m][((nt*4+kt)*2+v)*32 + lane] = W[m][(8kt+4v+tg)*32 + 8nt+g]
// where lane = 4g+tg. Makes every B-fragment load a 128B coalesced warp LDG.
// ---------------------------------------------------------------------------
__global__ void pc_permW(const float* __restrict__ W, float* __restrict__ Wp) {
    const size_t idx = (size_t)blockIdx.x * 256 + threadIdx.x;
    const int m = (int)(idx >> 10), t = (int)(idx & 1023);
    const int l = t & 31, q = t >> 5;
    const int v = q & 1, kt = (q >> 1) & 3, nt = q >> 3;
    const int g = l >> 2, tg = l & 3;
    Wp[idx] = W[(size_t)m * 1024 + (8 * kt + 4 * v + tg) * 32 + 8 * nt + g];
}

// Fragment load from permuted W (coalesced LDG).
#define LOAD_BFRAG(b, wp, nt, lane)                                          \
    _Pragma("unroll")                                                        \
    for (int kt = 0; kt < 4; kt++) {                                         \
        b[kt][0] = __float_as_uint((wp)[(((nt) * 4 + kt) * 2 + 0) * 32 + (lane)]); \
        b[kt][1] = __float_as_uint((wp)[(((nt) * 4 + kt) * 2 + 1) * 32 + (lane)]); \
    }

// Value slots (smem): row-major [b*36 + k], stride 36 -> conflict-free LDS.

// ---------------------------------------------------------------------------
// Leaf node (log-domain input p in slot): e=exp2((p-m)*L2E), Y'=e@W, m'=max.
// ---------------------------------------------------------------------------
template <int MT>
__device__ __forceinline__ void node_leaf(const float* pa, const float* __restrict__ wp,
                                          float* po, float* mo, int lane) {
    const int g = lane >> 2, tg = lane & 3;
    float a[MT][4][4];
#pragma unroll
    for (int mt = 0; mt < MT; mt++)
#pragma unroll
        for (int kt = 0; kt < 4; kt++)
#pragma unroll
            for (int r = 0; r < 4; r++)
                a[mt][kt][r] = pa[(16*mt + 8*(r&1) + g) * 36 + 8*kt + 4*(r>>1) + tg];

    float mx[MT][2];
#pragma unroll
    for (int mt = 0; mt < MT; mt++)
#pragma unroll
        for (int u = 0; u < 2; u++) {
            float m = fmaxf(a[mt][0][u], a[mt][0][u+2]);
#pragma unroll
            for (int kt = 1; kt < 4; kt++)
                m = fmaxf(m, fmaxf(a[mt][kt][u], a[mt][kt][u+2]));
            m = fmaxf(m, __shfl_xor_sync(0xffffffffu, m, 1));
            m = fmaxf(m, __shfl_xor_sync(0xffffffffu, m, 2));
            mx[mt][u] = m;
        }
#pragma unroll
    for (int mt = 0; mt < MT; mt++)
#pragma unroll
        for (int kt = 0; kt < 4; kt++)
#pragma unroll
            for (int r = 0; r < 4; r++)
                a[mt][kt][r] = ex2f(fmaf(a[mt][kt][r], L2E, -mx[mt][r&1] * L2E));

#pragma unroll
    for (int nt = 0; nt < 4; nt++) {
        uint32_t b[4][2];
        LOAD_BFRAG(b, wp, nt, lane);
#pragma unroll
        for (int mt = 0; mt < MT; mt++) {
            float c[4] = {0.f, 0.f, 0.f, 0.f};
#pragma unroll
            for (int kt = 0; kt < 4; kt++) mma_tf32(c, a[mt][kt], b[kt]);
#pragma unroll
            for (int u = 0; u < 2; u++)
                *(float2*)(po + (16*mt + 8*u + g) * 36 + 8*nt + 2*tg) =
                    make_float2(c[2*u], c[2*u+1]);
        }
    }
#pragma unroll
    for (int mt = 0; mt < MT; mt++)
#pragma unroll
        for (int u = 0; u < 2; u++)
            if (tg == 0) mo[16*mt + 8*u + g] = mx[mt][u];
}

// ---------------------------------------------------------------------------
// Linear node: e = (Yl*Yr)/max, Y'=e@W, m' = ml+mr+ln(max).
// PRE: slot already holds the product and mbuf the summed m.
// ---------------------------------------------------------------------------
template <int MT, bool PRE>
__device__ __forceinline__ void node_lin(const float* pa, const float* pb,
                                         const float* ma, const float* mb,
                                         const float* __restrict__ wp,
                                         float* po, float* mo, int lane) {
    const int g = lane >> 2, tg = lane & 3;
    float a[MT][4][4];
#pragma unroll
    for (int mt = 0; mt < MT; mt++)
#pragma unroll
        for (int kt = 0; kt < 4; kt++)
#pragma unroll
            for (int r = 0; r < 4; r++) {
                const int off = (16*mt + 8*(r&1) + g) * 36 + 8*kt + 4*(r>>1) + tg;
                float v = pa[off];
                if constexpr (!PRE) v *= pb[off];
                a[mt][kt][r] = v;
            }
    float ms[MT][2];
#pragma unroll
    for (int mt = 0; mt < MT; mt++)
#pragma unroll
        for (int u = 0; u < 2; u++) {
            const int row = 16*mt + 8*u + g;
            float mm = ma[row];
            if constexpr (!PRE) mm += mb[row];
            ms[mt][u] = mm;
        }
    float Mx[MT][2], rv[MT][2];
#pragma unroll
    for (int mt = 0; mt < MT; mt++)
#pragma unroll
        for (int u = 0; u < 2; u++) {
            float m = fmaxf(a[mt][0][u], a[mt][0][u+2]);
#pragma unroll
            for (int kt = 1; kt < 4; kt++)
                m = fmaxf(m, fmaxf(a[mt][kt][u], a[mt][kt][u+2]));
            m = fmaxf(m, __shfl_xor_sync(0xffffffffu, m, 1));
            m = fmaxf(m, __shfl_xor_sync(0xffffffffu, m, 2));
            Mx[mt][u] = m;
            rv[mt][u] = rcpf(m);
        }
#pragma unroll
    for (int mt = 0; mt < MT; mt++)
#pragma unroll
        for (int kt = 0; kt < 4; kt++)
#pragma unroll
            for (int r = 0; r < 4; r++)
                a[mt][kt][r] *= rv[mt][r&1];

#pragma unroll
    for (int nt = 0; nt < 4; nt++) {
        uint32_t b[4][2];
        LOAD_BFRAG(b, wp, nt, lane);
#pragma unroll
        for (int mt = 0; mt < MT; mt++) {
            float c[4] = {0.f, 0.f, 0.f, 0.f};
#pragma unroll
            for (int kt = 0; kt < 4; kt++) mma_tf32(c, a[mt][kt], b[kt]);
#pragma unroll
            for (int u = 0; u < 2; u++)
                *(float2*)(po + (16*mt + 8*u + g) * 36 + 8*nt + 2*tg) =
                    make_float2(c[2*u], c[2*u+1]);
        }
    }
#pragma unroll
    for (int mt = 0; mt < MT; mt++)
#pragma unroll
        for (int u = 0; u < 2; u++)
            if (tg == 0)
                mo[16*mt + 8*u + g] = fmaf(lg2f(Mx[mt][u]), LN2, ms[mt][u]);
}

// ---------------------------------------------------------------------------
// Stage sibling pairs into slots: slot n = child(2n) (+ or *) child(2n+1).
// ---------------------------------------------------------------------------
template <int IN_F, int MT, int NS, bool MULT>
__device__ __forceinline__ void stage_pairs(const float* __restrict__ src,
                                            float* val, int w, int lane) {
    constexpr int VS = MT * 16 * 36;
    const int k4 = lane & 7, bo = lane >> 3;
#pragma unroll
    for (int ns = 0; ns < NS; ns++) {
        const int n = NS * w + ns;
        float* slot = val + n * VS;
        const float4* xA = (const float4*)(src + (size_t)(2 * n) * 32);
        const float4* xB = xA + 8;
#pragma unroll
        for (int i = 0; i < MT * 4; i++) {
            const int bb = i * 4 + bo;
            const size_t roff = (size_t)bb * IN_F * 8;
            float4 va = xA[roff + k4], vb = xB[roff + k4];
            float4 p;
            if (MULT) p = make_float4(va.x*vb.x, va.y*vb.y, va.z*vb.z, va.w*vb.w);
            else      p = make_float4(va.x+vb.x, va.y+vb.y, va.z+vb.z, va.w+vb.w);
            *(float4*)(slot + bb * 36 + 4 * k4) = p;
        }
    }
}

// ---------------------------------------------------------------------------
// K1: x (log) -> 16-leaf subtree root (Y, m). Grid (128, 16), 4 warps.
// ---------------------------------------------------------------------------
template <int IN_F, int MT>
__global__ void __launch_bounds__(128, 5)
pc_k1(const float* __restrict__ in, const float* __restrict__ Wp,
      float* __restrict__ outY, float* __restrict__ outM) {
    constexpr int VS = MT * 16 * 36, NB = MT * 16, OUT_F = IN_F / 16;
    extern __shared__ float sm[];
    float* val  = sm;
    float* mbuf = sm + 8 * VS;
    const int s = blockIdx.x, B0 = blockIdx.y * NB;
    const int tid = threadIdx.x, w = tid >> 5, lane = tid & 31;
    const int o0 = 2048 - IN_F, o1 = o0 + IN_F/2, o2 = o1 + IN_F/4, o3 = o2 + IN_F/8;

    stage_pairs<IN_F, MT, 2, false>(in + ((size_t)B0 * IN_F + s * 16) * 32, val, w, lane);
    __syncthreads();

    node_leaf<MT>(val + w*VS, Wp + (size_t)(o0 + s*8 + w)*1024,
                  val + w*VS, mbuf + w*NB, lane);
    node_leaf<MT>(val + (4+w)*VS, Wp + (size_t)(o0 + s*8 + 4 + w)*1024,
                  val + (4+w)*VS, mbuf + (4+w)*NB, lane);
    __syncthreads();

    node_lin<MT, false>(val + 2*w*VS, val + (2*w+1)*VS, mbuf + 2*w*NB, mbuf + (2*w+1)*NB,
                        Wp + (size_t)(o1 + s*4 + w)*1024, val + 2*w*VS, mbuf + 2*w*NB, lane);
    __syncthreads();

    if (w < 2)
        node_lin<MT, false>(val + 4*w*VS, val + (4*w+2)*VS, mbuf + 4*w*NB, mbuf + (4*w+2)*NB,
                            Wp + (size_t)(o2 + s*2 + w)*1024, val + 4*w*VS, mbuf + 4*w*NB, lane);
    __syncthreads();

    if (w == 0)
        node_lin<MT, false>(val, val + 4*VS, mbuf, mbuf + 4*NB,
                            Wp + (size_t)(o3 + s)*1024, val, mbuf, lane);
    __syncthreads();

#pragma unroll
    for (int i = 0; i < MT; i++) {
        const int idx = tid + i * 128;
        const int bb = idx >> 3, k4 = idx & 7;
        float4 v = *(const float4*)(val + bb * 36 + 4 * k4);
        *(float4*)(outY + ((size_t)(B0 + bb) * OUT_F + s) * 32 + 4 * k4) = v;
    }
    if (tid < NB) outM[(size_t)(B0 + tid) * OUT_F + s] = mbuf[tid];
}

// ---------------------------------------------------------------------------
// K2T: (Y,m)[F=128] -> final output, fused. Grid 32 blocks x 8 warps, 16
// batches/block. Each warp owns a complete 16-leaf subtree (15 nodes,
// NO barriers, full ILP); last 3 levels + mixture cross-warp.
// ---------------------------------------------------------------------------
__global__ void __launch_bounds__(256, 1)
pc_k2t(const float* __restrict__ inY, const float* __restrict__ inM,
       const float* __restrict__ Wp, const float* __restrict__ mlw,
       float* __restrict__ outp) {
    constexpr int VS = 16 * 36;   // MT=1 slot: 576 floats
    constexpr int NB = 16;
    extern __shared__ float sm[];
    float* wval = sm;                         // 8 warps x 8 slots x 576
    float* wmb  = sm + 64 * VS;               // 8 x 8 x 16
    float* tval = wmb + 8 * 8 * NB;           // 8 slots x 576
    float* tmb  = tval + 8 * VS;              // 8 x 16
    float* lw   = tmb + 8 * NB;               // 32

    const int B0 = blockIdx.x * NB;
    const int tid = threadIdx.x, w = tid >> 5, lane = tid & 31;
    float* mv = wval + w * 8 * VS;
    float* mm = wmb + w * 8 * NB;

    // ---- stage: warp's 16 leaves (8 product slots + summed m) ----
    stage_pairs<128, 1, 8, true>(inY + ((size_t)B0 * 128 + w * 16) * 32, mv, 0, lane);
#pragma unroll
    for (int t = 0; t < 4; t++) {
        const int idx = lane + t * 32;
        const int n = idx >> 4, b = idx & 15;
        mm[n * NB + b] = inM[(size_t)(B0 + b) * 128 + w * 16 + 2 * n]
                       + inM[(size_t)(B0 + b) * 128 + w * 16 + 2 * n + 1];
    }
    if (tid < 32) lw[tid] = mlw[tid];

    // ---- warp-private subtree fold: 15 nodes, no barriers ----
    const int o0 = 1920, o1 = 1984, o2 = 2016, o3 = 2032;
#pragma unroll 2
    for (int j = 0; j < 8; j++)
        node_lin<1, true>(mv + j*VS, nullptr, mm + j*NB, nullptr,
                          Wp + (size_t)(o0 + 8*w + j)*1024, mv + j*VS, mm + j*NB, lane);
#pragma unroll 2
    for (int j = 0; j < 4; j++)
        node_lin<1, false>(mv + 2*j*VS, mv + (2*j+1)*VS, mm + 2*j*NB, mm + (2*j+1)*NB,
                           Wp + (size_t)(o1 + 4*w + j)*1024, mv + 2*j*VS, mm + 2*j*NB, lane);
#pragma unroll
    for (int j = 0; j < 2; j++)
        node_lin<1, false>(mv + 4*j*VS, mv + (4*j+2)*VS, mm + 4*j*NB, mm + (4*j+2)*NB,
                           Wp + (size_t)(o2 + 2*w + j)*1024, mv + 4*j*VS, mm + 4*j*NB, lane);
    node_lin<1, false>(mv, mv + 4*VS, mm, mm + 4*NB,
                       Wp + (size_t)(o3 + w)*1024, tval + w*VS, tmb + w*NB, lane);
    __syncthreads();

    // ---- cross-warp tail: 8 -> 4 -> 2 -> 1 ----
    if (w < 4)
        node_lin<1, false>(tval + 2*w*VS, tval + (2*w+1)*VS, tmb + 2*w*NB, tmb + (2*w+1)*NB,
                           Wp + (size_t)(2040 + w)*1024, tval + 2*w*VS, tmb + 2*w*NB, lane);
    __syncthreads();
    if (w < 2)
        node_lin<1, false>(tval + 4*w*VS, tval + (4*w+2)*VS, tmb + 4*w*NB, tmb + (4*w+2)*NB,
                           Wp + (size_t)(2044 + w)*1024, tval + 4*w*VS, tmb + 4*w*NB, lane);
    __syncthreads();
    if (w == 0)
        node_lin<1, false>(tval, tval + 4*VS, tmb, tmb + 4*NB,
                           Wp + (size_t)2046*1024, tval, tmb, lane);
    __syncthreads();

    // ---- mixture: out[b] = logsumexp(2*(ln Y + m) + log_softmax(mlw)) ----
    if (tid < NB) {
        const int b = tid;
        float m1 = lw[0];
        for (int k = 1; k < 32; k++) m1 = fmaxf(m1, lw[k]);
        float s1 = 0.f;
        for (int k = 0; k < 32; k++) s1 += ex2f((lw[k] - m1) * L2E);
        const float lse = fmaf(lg2f(s1), LN2, m1);
        const float mr = tmb[b];

        float t[32];
        float m2 = -1e30f;
        for (int k = 0; k < 32; k++) {
            t[k] = 2.f * fmaf(lg2f(tval[b * 36 + k]), LN2, mr) + lw[k] - lse;
            m2 = fmaxf(m2, t[k]);
        }
        float s2 = 0.f;
        for (int k = 0; k < 32; k++) s2 += ex2f((t[k] - m2) * L2E);
        outp[B0 + b] = fmaf(lg2f(s2), LN2, m2);
    }
}

// ---------------------------------------------------------------------------
// Launch. Inputs: x f32[512,2048,32], weights f32[2047,32,32],
// fold_idx i32 (trivial (2f,2f+1) pairing -> computed), mix_logw f32[32].
// Output: f32[512].
// ---------------------------------------------------------------------------
extern "C" void kernel_launch(void* const* d_in, const int* in_sizes, int n_in,
                              void* d_out, int out_size) {
    const float* x   = (const float*)d_in[0];
    const float* W   = (const float*)d_in[1];
    const float* mlw = (const float*)d_in[3];
    float* out = (float*)d_out;

    float *y1, *m1, *wp;
    cudaGetSymbolAddress((void**)&y1, g_Y1);
    cudaGetSymbolAddress((void**)&m1, g_m1);
    cudaGetSymbolAddress((void**)&wp, g_Wp);

    const int smem_k1  = (8 * 1152 + 8 * 32) * sizeof(float);               // 37888 B
    const int smem_k2t = (64 * 576 + 8 * 8 * 16 + 8 * 576 + 8 * 16 + 32)
                         * sizeof(float);                                    // 170624 B

    cudaFuncSetAttribute((const void*)pc_k1<2048, 2>,
                         cudaFuncAttributeMaxDynamicSharedMemorySize, smem_k1);
    cudaFuncSetAttribute((const void*)pc_k2t,
                         cudaFuncAttributeMaxDynamicSharedMemorySize, smem_k2t);

    pc_permW      <<<8188,          256>>>(W, wp);
    pc_k1<2048, 2><<<dim3(128, 16), 128, smem_k1>>>(x, wp, y1, m1);
    pc_k2t        <<<32,            256, smem_k2t>>>(y1, m1, wp, mlw, out);
}

// round 15
// speedup vs baseline: 1.1152x; 1.1152x over previous
#include <cuda_runtime.h>
#include <cstdint>

#define L2E 1.4426950408889634f
#define LN2 0.6931471805599453f

// Inter-kernel (Y, m) scratch + permuted weights (static device mem: allowed)
__device__ float g_Y1[(size_t)512 * 128 * 32];   // 8 MB
__device__ float g_m1[(size_t)512 * 128];
__device__ float g_Y2[(size_t)512 * 8 * 32];
__device__ float g_m2[(size_t)512 * 8];
__device__ float g_Wp[(size_t)2047 * 1024];      // 8 MB, fragment-ordered W

// ---------------------------------------------------------------------------
__device__ __forceinline__ float ex2f(float x) {
    float r; asm("ex2.approx.f32 %0, %1;" : "=f"(r) : "f"(x)); return r;
}
__device__ __forceinline__ float lg2f(float x) {
    float r; asm("lg2.approx.f32 %0, %1;" : "=f"(r) : "f"(x)); return r;
}
__device__ __forceinline__ float rcpf(float x) {
    float r; asm("rcp.approx.f32 %0, %1;" : "=f"(r) : "f"(x)); return r;
}
__device__ __forceinline__ void cp_async16(uint32_t dst, const void* src) {
    asm volatile("cp.async.cg.shared.global [%0], [%1], 16;" :: "r"(dst), "l"(src));
}
__device__ __forceinline__ void cp_commit() {
    asm volatile("cp.async.commit_group;");
}
template <int N>
__device__ __forceinline__ void cp_wait() {
    asm volatile("cp.async.wait_group %0;" :: "n"(N));
}
__device__ __forceinline__ uint32_t s2u(const void* p) {
    return (uint32_t)__cvta_generic_to_shared(p);
}
// m16n8k8 tf32 mma, D += A*B (A passed as f32, truncated by HW)
__device__ __forceinline__ void mma_tf32(float c[4], const float a[4], const uint32_t b[2]) {
    asm("mma.sync.aligned.m16n8k8.row.col.f32.tf32.tf32.f32 "
        "{%0,%1,%2,%3}, {%4,%5,%6,%7}, {%8,%9}, {%0,%1,%2,%3};"
        : "+f"(c[0]), "+f"(c[1]), "+f"(c[2]), "+f"(c[3])
        : "r"(__float_as_uint(a[0])), "r"(__float_as_uint(a[1])),
          "r"(__float_as_uint(a[2])), "r"(__float_as_uint(a[3])),
          "r"(b[0]), "r"(b[1]));
}

// ---------------------------------------------------------------------------
// W permute: Wp[m][((nt*4+kt)*2+v)*32 + lane] = W[m][(8kt+4v+tg)*32 + 8nt+g],
// lane = 4g+tg. Each thread owns ONE within-matrix slot t and walks 8
// consecutive matrices -> 8 independent LDG/STG in flight (MLP=8); stores
// coalesced. Makes every B-fragment load a 128B coalesced warp access.
// ---------------------------------------------------------------------------
__global__ void pc_permW(const float* __restrict__ W, float* __restrict__ Wp) {
    const int gt = blockIdx.x * 256 + threadIdx.x;   // 0..262143
    const int t  = gt & 1023;                        // within-matrix dst slot
    const int m0 = (gt >> 10) * 8;                   // first of 8 matrices
    const int l = t & 31, q = t >> 5;
    const int v = q & 1, kt = (q >> 1) & 3, nt = q >> 3;
    const int g = l >> 2, tg = l & 3;
    const int soff = (8 * kt + 4 * v + tg) * 32 + 8 * nt + g;

    float r[8];
#pragma unroll
    for (int i = 0; i < 8; i++) {
        const int m = m0 + i;
        if (m < 2047) r[i] = W[(size_t)m * 1024 + soff];
    }
#pragma unroll
    for (int i = 0; i < 8; i++) {
        const int m = m0 + i;
        if (m < 2047) Wp[(size_t)m * 1024 + t] = r[i];
    }
}

// Fragment load from permuted W (global LDG or smem LDS, both coalesced/CF).
#define LOAD_BFRAG(b, wp, nt, lane)                                          \
    _Pragma("unroll")                                                        \
    for (int kt = 0; kt < 4; kt++) {                                         \
        b[kt][0] = __float_as_uint((wp)[(((nt) * 4 + kt) * 2 + 0) * 32 + (lane)]); \
        b[kt][1] = __float_as_uint((wp)[(((nt) * 4 + kt) * 2 + 1) * 32 + (lane)]); \
    }

// Value slots (smem): row-major [b*36 + k], stride 36 -> conflict-free LDS.

// ---------------------------------------------------------------------------
// Leaf node (log-domain input p in slot): e=exp2((p-m)*L2E), Y'=e@W, m'=max.
// ---------------------------------------------------------------------------
template <int MT>
__device__ __forceinline__ void node_leaf(const float* pa, const float* __restrict__ wp,
                                          float* po, float* mo, int lane) {
    const int g = lane >> 2, tg = lane & 3;
    float a[MT][4][4];
#pragma unroll
    for (int mt = 0; mt < MT; mt++)
#pragma unroll
        for (int kt = 0; kt < 4; kt++)
#pragma unroll
            for (int r = 0; r < 4; r++)
                a[mt][kt][r] = pa[(16*mt + 8*(r&1) + g) * 36 + 8*kt + 4*(r>>1) + tg];

    float mx[MT][2];
#pragma unroll
    for (int mt = 0; mt < MT; mt++)
#pragma unroll
        for (int u = 0; u < 2; u++) {
            float m = fmaxf(a[mt][0][u], a[mt][0][u+2]);
#pragma unroll
            for (int kt = 1; kt < 4; kt++)
                m = fmaxf(m, fmaxf(a[mt][kt][u], a[mt][kt][u+2]));
            m = fmaxf(m, __shfl_xor_sync(0xffffffffu, m, 1));
            m = fmaxf(m, __shfl_xor_sync(0xffffffffu, m, 2));
            mx[mt][u] = m;
        }
#pragma unroll
    for (int mt = 0; mt < MT; mt++)
#pragma unroll
        for (int kt = 0; kt < 4; kt++)
#pragma unroll
            for (int r = 0; r < 4; r++)
                a[mt][kt][r] = ex2f(fmaf(a[mt][kt][r], L2E, -mx[mt][r&1] * L2E));

#pragma unroll
    for (int nt = 0; nt < 4; nt++) {
        uint32_t b[4][2];
        LOAD_BFRAG(b, wp, nt, lane);
#pragma unroll
        for (int mt = 0; mt < MT; mt++) {
            float c[4] = {0.f, 0.f, 0.f, 0.f};
#pragma unroll
            for (int kt = 0; kt < 4; kt++) mma_tf32(c, a[mt][kt], b[kt]);
#pragma unroll
            for (int u = 0; u < 2; u++)
                *(float2*)(po + (16*mt + 8*u + g) * 36 + 8*nt + 2*tg) =
                    make_float2(c[2*u], c[2*u+1]);
        }
    }
#pragma unroll
    for (int mt = 0; mt < MT; mt++)
#pragma unroll
        for (int u = 0; u < 2; u++)
            if (tg == 0) mo[16*mt + 8*u + g] = mx[mt][u];
}

// ---------------------------------------------------------------------------
// Linear node: e = (Yl*Yr)/max, Y'=e@W, m' = ml+mr+ln(max).
// PRE: slot already holds the product and mbuf the summed m.
// ---------------------------------------------------------------------------
template <int MT, bool PRE>
__device__ __forceinline__ void node_lin(const float* pa, const float* pb,
                                         const float* ma, const float* mb,
                                         const float* __restrict__ wp,
                                         float* po, float* mo, int lane) {
    const int g = lane >> 2, tg = lane & 3;
    float a[MT][4][4];
#pragma unroll
    for (int mt = 0; mt < MT; mt++)
#pragma unroll
        for (int kt = 0; kt < 4; kt++)
#pragma unroll
            for (int r = 0; r < 4; r++) {
                const int off = (16*mt + 8*(r&1) + g) * 36 + 8*kt + 4*(r>>1) + tg;
                float v = pa[off];
                if constexpr (!PRE) v *= pb[off];
                a[mt][kt][r] = v;
            }
    float ms[MT][2];
#pragma unroll
    for (int mt = 0; mt < MT; mt++)
#pragma unroll
        for (int u = 0; u < 2; u++) {
            const int row = 16*mt + 8*u + g;
            float mm = ma[row];
            if constexpr (!PRE) mm += mb[row];
            ms[mt][u] = mm;
        }
    float Mx[MT][2], rv[MT][2];
#pragma unroll
    for (int mt = 0; mt < MT; mt++)
#pragma unroll
        for (int u = 0; u < 2; u++) {
            float m = fmaxf(a[mt][0][u], a[mt][0][u+2]);
#pragma unroll
            for (int kt = 1; kt < 4; kt++)
                m = fmaxf(m, fmaxf(a[mt][kt][u], a[mt][kt][u+2]));
            m = fmaxf(m, __shfl_xor_sync(0xffffffffu, m, 1));
            m = fmaxf(m, __shfl_xor_sync(0xffffffffu, m, 2));
            Mx[mt][u] = m;
            rv[mt][u] = rcpf(m);
        }
#pragma unroll
    for (int mt = 0; mt < MT; mt++)
#pragma unroll
        for (int kt = 0; kt < 4; kt++)
#pragma unroll
            for (int r = 0; r < 4; r++)
                a[mt][kt][r] *= rv[mt][r&1];

#pragma unroll
    for (int nt = 0; nt < 4; nt++) {
        uint32_t b[4][2];
        LOAD_BFRAG(b, wp, nt, lane);
#pragma unroll
        for (int mt = 0; mt < MT; mt++) {
            float c[4] = {0.f, 0.f, 0.f, 0.f};
#pragma unroll
            for (int kt = 0; kt < 4; kt++) mma_tf32(c, a[mt][kt], b[kt]);
#pragma unroll
            for (int u = 0; u < 2; u++)
                *(float2*)(po + (16*mt + 8*u + g) * 36 + 8*nt + 2*tg) =
                    make_float2(c[2*u], c[2*u+1]);
        }
    }
#pragma unroll
    for (int mt = 0; mt < MT; mt++)
#pragma unroll
        for (int u = 0; u < 2; u++)
            if (tg == 0)
                mo[16*mt + 8*u + g] = fmaf(lg2f(Mx[mt][u]), LN2, ms[mt][u]);
}

// ---------------------------------------------------------------------------
// Stage sibling pairs into slots: slot n = child(2n) (+ or *) child(2n+1).
// ---------------------------------------------------------------------------
template <int IN_F, int MT, int NS, bool MULT>
__device__ __forceinline__ void stage_pairs(const float* __restrict__ src,
                                            float* val, int w, int lane) {
    constexpr int VS = MT * 16 * 36;
    const int k4 = lane & 7, bo = lane >> 3;
#pragma unroll
    for (int ns = 0; ns < NS; ns++) {
        const int n = NS * w + ns;
        float* slot = val + n * VS;
        const float4* xA = (const float4*)(src + (size_t)(2 * n) * 32);
        const float4* xB = xA + 8;
#pragma unroll
        for (int i = 0; i < MT * 4; i++) {
            const int bb = i * 4 + bo;
            const size_t roff = (size_t)bb * IN_F * 8;
            float4 va = xA[roff + k4], vb = xB[roff + k4];
            float4 p;
            if (MULT) p = make_float4(va.x*vb.x, va.y*vb.y, va.z*vb.z, va.w*vb.w);
            else      p = make_float4(va.x+vb.x, va.y+vb.y, va.z+vb.z, va.w+vb.w);
            *(float4*)(slot + bb * 36 + 4 * k4) = p;
        }
    }
}

// ---------------------------------------------------------------------------
// K1: x (log) -> 16-leaf subtree root (Y, m). Grid (128, 16), 4 warps.
// ---------------------------------------------------------------------------
template <int IN_F, int MT>
__global__ void __launch_bounds__(128, 5)
pc_k1(const float* __restrict__ in, const float* __restrict__ Wp,
      float* __restrict__ outY, float* __restrict__ outM) {
    constexpr int VS = MT * 16 * 36, NB = MT * 16, OUT_F = IN_F / 16;
    extern __shared__ float sm[];
    float* val  = sm;
    float* mbuf = sm + 8 * VS;
    const int s = blockIdx.x, B0 = blockIdx.y * NB;
    const int tid = threadIdx.x, w = tid >> 5, lane = tid & 31;
    const int o0 = 2048 - IN_F, o1 = o0 + IN_F/2, o2 = o1 + IN_F/4, o3 = o2 + IN_F/8;

    stage_pairs<IN_F, MT, 2, false>(in + ((size_t)B0 * IN_F + s * 16) * 32, val, w, lane);
    __syncthreads();

    node_leaf<MT>(val + w*VS, Wp + (size_t)(o0 + s*8 + w)*1024,
                  val + w*VS, mbuf + w*NB, lane);
    node_leaf<MT>(val + (4+w)*VS, Wp + (size_t)(o0 + s*8 + 4 + w)*1024,
                  val + (4+w)*VS, mbuf + (4+w)*NB, lane);
    __syncthreads();

    node_lin<MT, false>(val + 2*w*VS, val + (2*w+1)*VS, mbuf + 2*w*NB, mbuf + (2*w+1)*NB,
                        Wp + (size_t)(o1 + s*4 + w)*1024, val + 2*w*VS, mbuf + 2*w*NB, lane);
    __syncthreads();

    if (w < 2)
        node_lin<MT, false>(val + 4*w*VS, val + (4*w+2)*VS, mbuf + 4*w*NB, mbuf + (4*w+2)*NB,
                            Wp + (size_t)(o2 + s*2 + w)*1024, val + 4*w*VS, mbuf + 4*w*NB, lane);
    __syncthreads();

    if (w == 0)
        node_lin<MT, false>(val, val + 4*VS, mbuf, mbuf + 4*NB,
                            Wp + (size_t)(o3 + s)*1024, val, mbuf, lane);
    __syncthreads();

#pragma unroll
    for (int i = 0; i < MT; i++) {
        const int idx = tid + i * 128;
        const int bb = idx >> 3, k4 = idx & 7;
        float4 v = *(const float4*)(val + bb * 36 + 4 * k4);
        *(float4*)(outY + ((size_t)(B0 + bb) * OUT_F + s) * 32 + 4 * k4) = v;
    }
    if (tid < NB) outM[(size_t)(B0 + tid) * OUT_F + s] = mbuf[tid];
}

// ---------------------------------------------------------------------------
// K2: (Y,m)[128] -> (Y,m)[8]. All-linear. Grid (8, 16).
// W working set (15 matrices) cp.async'd to smem at start.
// ---------------------------------------------------------------------------
template <int MT>
__global__ void __launch_bounds__(128, 2)
pc_k2(const float* __restrict__ inY, const float* __restrict__ inM,
      const float* __restrict__ Wp,
      float* __restrict__ outY, float* __restrict__ outM) {
    constexpr int IN_F = 128, VS = MT * 16 * 36, NB = MT * 16, OUT_F = 8;
    extern __shared__ float sm[];
    float* val  = sm;                       // 8 * VS
    float* mbuf = sm + 8 * VS;              // 8 * NB
    float* wsm  = mbuf + 8 * NB;            // 15 * 1024
    const int s = blockIdx.x, B0 = blockIdx.y * NB;
    const int tid = threadIdx.x, w = tid >> 5, lane = tid & 31;
    const int o0 = 1920, o1 = 1984, o2 = 2016, o3 = 2032;

    {
        const uint32_t wsm_s = s2u(wsm);
#pragma unroll
        for (int t = 0; t < 30; t++) {
            const int c = tid + t * 128;
            const int slot = c >> 8, rc = c & 255;
            int gidx;
            if (slot < 8)       gidx = o0 + s * 8 + slot;
            else if (slot < 12) gidx = o1 + s * 4 + (slot - 8);
            else if (slot < 14) gidx = o2 + s * 2 + (slot - 12);
            else                gidx = o3 + s;
            cp_async16(wsm_s + (uint32_t)c * 16u, Wp + (size_t)gidx * 1024 + rc * 4);
        }
        cp_commit();
    }

    stage_pairs<IN_F, MT, 2, true>(inY + ((size_t)B0 * IN_F + s * 16) * 32, val, w, lane);
#pragma unroll
    for (int t = 0; t < (8 * NB) / 128; t++) {
        const int idx = tid + t * 128;
        const int n = idx / NB, b = idx % NB;
        mbuf[n * NB + b] = inM[(size_t)(B0 + b) * IN_F + s*16 + 2*n]
                         + inM[(size_t)(B0 + b) * IN_F + s*16 + 2*n + 1];
    }
    cp_wait<0>();
    __syncthreads();

    node_lin<MT, true>(val + w*VS, nullptr, mbuf + w*NB, nullptr,
                       wsm + w*1024, val + w*VS, mbuf + w*NB, lane);
    node_lin<MT, true>(val + (4+w)*VS, nullptr, mbuf + (4+w)*NB, nullptr,
                       wsm + (4+w)*1024, val + (4+w)*VS, mbuf + (4+w)*NB, lane);
    __syncthreads();

    node_lin<MT, false>(val + 2*w*VS, val + (2*w+1)*VS, mbuf + 2*w*NB, mbuf + (2*w+1)*NB,
                        wsm + (8+w)*1024, val + 2*w*VS, mbuf + 2*w*NB, lane);
    __syncthreads();

    if (w < 2)
        node_lin<MT, false>(val + 4*w*VS, val + (4*w+2)*VS, mbuf + 4*w*NB, mbuf + (4*w+2)*NB,
                            wsm + (12+w)*1024, val + 4*w*VS, mbuf + 4*w*NB, lane);
    __syncthreads();

    if (w == 0)
        node_lin<MT, false>(val, val + 4*VS, mbuf, mbuf + 4*NB,
                            wsm + 14*1024, val, mbuf, lane);
    __syncthreads();

#pragma unroll
    for (int i = 0; i < MT; i++) {
        const int idx = tid + i * 128;
        const int bb = idx >> 3, k4 = idx & 7;
        float4 v = *(const float4*)(val + bb * 36 + 4 * k4);
        *(float4*)(outY + ((size_t)(B0 + bb) * OUT_F + s) * 32 + 4 * k4) = v;
    }
    if (tid < NB) outM[(size_t)(B0 + tid) * OUT_F + s] = mbuf[tid];
}

// ---------------------------------------------------------------------------
// Tail: (Y,m)[8] -> root -> mixture logsumexp. Grid 16 x 128 thr, 32 batches.
// All 7 W matrices cp.async'd to smem.
// ---------------------------------------------------------------------------
__global__ void __launch_bounds__(128, 2)
pc_tail(const float* __restrict__ inY, const float* __restrict__ inM,
        const float* __restrict__ Wp, const float* __restrict__ mlw,
        float* __restrict__ outp) {
    constexpr int MT = 2, VS = 1152, NB = 32;
    extern __shared__ float sm[];
    float* val  = sm;             // 4 slots
    float* mbuf = sm + 4 * VS;    // 4 x 32
    float* lw   = mbuf + 4 * NB;  // 32
    float* wsm  = lw + 32;        // 7 * 1024
    const int B0 = blockIdx.x * NB;
    const int tid = threadIdx.x, w = tid >> 5, lane = tid & 31;

    {
        const uint32_t wsm_s = s2u(wsm);
        const float* src = Wp + (size_t)2040 * 1024;
#pragma unroll
        for (int t = 0; t < 14; t++) {
            const int c = tid + t * 128;
            cp_async16(wsm_s + (uint32_t)c * 16u, src + c * 4);
        }
        cp_commit();
    }

    stage_pairs<8, MT, 1, true>(inY + (size_t)B0 * 8 * 32, val, w, lane);
    {
        const int n = tid >> 5, b = tid & 31;
        mbuf[n * NB + b] = inM[(size_t)(B0 + b) * 8 + 2*n]
                         + inM[(size_t)(B0 + b) * 8 + 2*n + 1];
    }
    if (tid < 32) lw[tid] = mlw[tid];
    cp_wait<0>();
    __syncthreads();

    node_lin<MT, true>(val + w*VS, nullptr, mbuf + w*NB, nullptr,
                       wsm + w*1024, val + w*VS, mbuf + w*NB, lane);
    __syncthreads();

    if (w < 2)
        node_lin<MT, false>(val + 2*w*VS, val + (2*w+1)*VS, mbuf + 2*w*NB, mbuf + (2*w+1)*NB,
                            wsm + (4+w)*1024, val + 2*w*VS, mbuf + 2*w*NB, lane);
    __syncthreads();

    if (w == 0)
        node_lin<MT, false>(val, val + 2*VS, mbuf, mbuf + 2*NB,
                            wsm + 6*1024, val, mbuf, lane);
    __syncthreads();

    if (tid < 32) {
        const int b = tid;
        float m1 = lw[0];
        for (int k = 1; k < 32; k++) m1 = fmaxf(m1, lw[k]);
        float s1 = 0.f;
        for (int k = 0; k < 32; k++) s1 += ex2f((lw[k] - m1) * L2E);
        const float lse = fmaf(lg2f(s1), LN2, m1);
        const float mr = mbuf[b];

        float t[32];
        float m2 = -1e30f;
        for (int k = 0; k < 32; k++) {
            t[k] = 2.f * fmaf(lg2f(val[b * 36 + k]), LN2, mr) + lw[k] - lse;
            m2 = fmaxf(m2, t[k]);
        }
        float s2 = 0.f;
        for (int k = 0; k < 32; k++) s2 += ex2f((t[k] - m2) * L2E);
        outp[B0 + b] = fmaf(lg2f(s2), LN2, m2);
    }
}

// ---------------------------------------------------------------------------
// Launch. Inputs: x f32[512,2048,32], weights f32[2047,32,32],
// fold_idx i32 (trivial (2f,2f+1) pairing -> computed), mix_logw f32[32].
// Output: f32[512].
// ---------------------------------------------------------------------------
extern "C" void kernel_launch(void* const* d_in, const int* in_sizes, int n_in,
                              void* d_out, int out_size) {
    const float* x   = (const float*)d_in[0];
    const float* W   = (const float*)d_in[1];
    const float* mlw = (const float*)d_in[3];
    float* out = (float*)d_out;

    float *y1, *m1, *y2, *m2, *wp;
    cudaGetSymbolAddress((void**)&y1, g_Y1);
    cudaGetSymbolAddress((void**)&m1, g_m1);
    cudaGetSymbolAddress((void**)&y2, g_Y2);
    cudaGetSymbolAddress((void**)&m2, g_m2);
    cudaGetSymbolAddress((void**)&wp, g_Wp);

    const int smem_k1 = (8 * 1152 + 8 * 32) * sizeof(float);                  // 37888 B
    const int smem_k2 = (8 * 1152 + 8 * 32 + 15 * 1024) * sizeof(float);      // 99328 B
    const int smem_t  = (4 * 1152 + 4 * 32 + 32 + 7 * 1024) * sizeof(float);  // 47744 B

    cudaFuncSetAttribute((const void*)pc_k1<2048, 2>,
                         cudaFuncAttributeMaxDynamicSharedMemorySize, smem_k1);
    cudaFuncSetAttribute((const void*)pc_k2<2>,
                         cudaFuncAttributeMaxDynamicSharedMemorySize, smem_k2);
    cudaFuncSetAttribute((const void*)pc_tail,
                         cudaFuncAttributeMaxDynamicSharedMemorySize, smem_t);

    pc_permW      <<<1024,          256>>>(W, wp);
    pc_k1<2048, 2><<<dim3(128, 16), 128, smem_k1>>>(x, wp, y1, m1);
    pc_k2<2>      <<<dim3(8, 16),   128, smem_k2>>>(y1, m1, wp, y2, m2);
    pc_tail       <<<16,            128, smem_t>>>(y2, m2, wp, mlw, out);
}